// round 1
// baseline (speedup 1.0000x reference)
#include <cuda_runtime.h>
#include <cstdint>

#define B 8
#define K 19
#define C 512
#define S 16384

// Scratch: unnormalized exp(aux - rowmax), plus per-row 1/sum.
__device__ float g_probs[B * K * S];
__device__ float g_invsum[B * K];

// ---------------------------------------------------------------------------
// Kernel 1: per-(b,k) row: rowmax, e = exp(x - max) -> g_probs, 1/sum(e).
// 152 blocks x 256 threads. ~30 MB traffic total, trivial cost.
// ---------------------------------------------------------------------------
__global__ void __launch_bounds__(256) softmax_stats_kernel(const float* __restrict__ aux) {
    const int row = blockIdx.x;                       // 0..151  (= b*19 + k)
    const float4* __restrict__ src = (const float4*)(aux + (size_t)row * S);
    float4* __restrict__ dst = (float4*)(g_probs + (size_t)row * S);
    const int tid = threadIdx.x;
    __shared__ float sred[32];
    __shared__ float smax;

    // phase 1: row max
    float m = -1e30f;
    #pragma unroll 4
    for (int i = tid; i < S / 4; i += 256) {
        float4 v = src[i];
        m = fmaxf(m, fmaxf(fmaxf(v.x, v.y), fmaxf(v.z, v.w)));
    }
    #pragma unroll
    for (int o = 16; o; o >>= 1) m = fmaxf(m, __shfl_xor_sync(0xffffffffu, m, o));
    if ((tid & 31) == 0) sred[tid >> 5] = m;
    __syncthreads();
    if (tid == 0) {
        float v = sred[0];
        #pragma unroll
        for (int w = 1; w < 8; ++w) v = fmaxf(v, sred[w]);
        smax = v;
    }
    __syncthreads();
    const float mx = smax;

    // phase 2: e = exp(x - mx), write unnormalized, accumulate sum
    float sum = 0.f;
    #pragma unroll 4
    for (int i = tid; i < S / 4; i += 256) {
        float4 v = src[i];
        float4 e;
        e.x = __expf(v.x - mx);
        e.y = __expf(v.y - mx);
        e.z = __expf(v.z - mx);
        e.w = __expf(v.w - mx);
        dst[i] = e;
        sum += (e.x + e.y) + (e.z + e.w);
    }
    #pragma unroll
    for (int o = 16; o; o >>= 1) sum += __shfl_xor_sync(0xffffffffu, sum, o);
    if ((tid & 31) == 0) sred[tid >> 5] = sum;
    __syncthreads();
    if (tid == 0) {
        float t = 0.f;
        #pragma unroll
        for (int w = 0; w < 8; ++w) t += sred[w];
        g_invsum[row] = 1.0f / t;
    }
}

// ---------------------------------------------------------------------------
// Kernel 2: ctx[b,k,c] = invsum[b,k] * sum_s e[b,k,s] * feats[b,c,s]
// Block: 256 threads = 8 warps. Warp owns 4 channels; lanes split s (coalesced
// float4 loads). Per-thread register tile: 19 k x 4 c, one f32x2 accumulator
// each (packed-pair FMA doubles fp32 throughput). Grid (16 c-tiles, 8 b).
// ---------------------------------------------------------------------------
__device__ __forceinline__ void fma2(unsigned long long& acc,
                                     unsigned long long a,
                                     unsigned long long b) {
    asm("fma.rn.f32x2 %0, %1, %2, %3;" : "=l"(acc) : "l"(a), "l"(b), "l"(acc));
}

__global__ void __launch_bounds__(256, 1) gather_kernel(const float* __restrict__ feats,
                                                        float* __restrict__ out) {
    const int b    = blockIdx.y;
    const int warp = threadIdx.x >> 5;
    const int lane = threadIdx.x & 31;
    const int c_base = blockIdx.x * 32 + warp * 4;

    const ulonglong2* __restrict__ p0 =
        (const ulonglong2*)(g_probs + (size_t)b * K * S);
    const ulonglong2* __restrict__ f0 =
        (const ulonglong2*)(feats + (size_t)(b * C + c_base) * S);
    const int frow = S / 4;  // row stride in float4 units

    unsigned long long acc[K][4];
    #pragma unroll
    for (int k = 0; k < K; ++k)
        #pragma unroll
        for (int j = 0; j < 4; ++j) acc[k][j] = 0ULL;

    #pragma unroll 1
    for (int i = 0; i < S / 4 / 32; ++i) {  // 128 iterations
        const int idx = i * 32 + lane;
        ulonglong2 fv0 = f0[0 * frow + idx];
        ulonglong2 fv1 = f0[1 * frow + idx];
        ulonglong2 fv2 = f0[2 * frow + idx];
        ulonglong2 fv3 = f0[3 * frow + idx];
        #pragma unroll
        for (int k = 0; k < K; ++k) {
            ulonglong2 pv = p0[k * frow + idx];
            fma2(acc[k][0], pv.x, fv0.x);
            fma2(acc[k][1], pv.x, fv1.x);
            fma2(acc[k][2], pv.x, fv2.x);
            fma2(acc[k][3], pv.x, fv3.x);
            fma2(acc[k][0], pv.y, fv0.y);
            fma2(acc[k][1], pv.y, fv1.y);
            fma2(acc[k][2], pv.y, fv2.y);
            fma2(acc[k][3], pv.y, fv3.y);
        }
    }

    // Epilogue: pair-add, warp butterfly reduce, scale by invsum, store.
    #pragma unroll
    for (int k = 0; k < K; ++k) {
        const float inv = g_invsum[b * K + k];
        #pragma unroll
        for (int j = 0; j < 4; ++j) {
            float2 v = *(float2*)&acc[k][j];
            float s = v.x + v.y;
            s += __shfl_xor_sync(0xffffffffu, s, 16);
            s += __shfl_xor_sync(0xffffffffu, s, 8);
            s += __shfl_xor_sync(0xffffffffu, s, 4);
            s += __shfl_xor_sync(0xffffffffu, s, 2);
            s += __shfl_xor_sync(0xffffffffu, s, 1);
            if (lane == ((k * 4 + j) & 31))
                out[(size_t)(b * C + c_base + j) * K + k] = s * inv;
        }
    }
}

// ---------------------------------------------------------------------------
extern "C" void kernel_launch(void* const* d_in, const int* in_sizes, int n_in,
                              void* d_out, int out_size) {
    const float* feats = (const float*)d_in[0];  // [8,512,128,128]
    const float* aux   = (const float*)d_in[1];  // [8,19,128,128]
    float* out = (float*)d_out;                  // [8,512,19,1]

    softmax_stats_kernel<<<B * K, 256>>>(aux);
    dim3 grid(C / 32, B);
    gather_kernel<<<grid, 256>>>(feats, out);
}